// round 1
// baseline (speedup 1.0000x reference)
#include <cuda_runtime.h>

#define TT   64
#define BATCH 8192
#define DIN  128
#define BT   64
#define NTH  256
#define NCTA (BATCH / BT)

#define G1 128
#define G2 64
#define G3 32
#define H1 32
#define H2 16
#define H3 8

// shared-memory float offsets
#define OFF_W1X 0        // [128][128]
#define OFF_W1H 16384    // [32][128]
#define OFF_B1  20480    // [128]
#define OFF_W2X 20608    // [32][64]
#define OFF_W2H 22656    // [16][64]
#define OFF_B2  23680    // [64]
#define OFF_W3X 23744    // [16][32]
#define OFF_W3H 24256    // [8][32]
#define OFF_B3  24512    // [32]
#define OFF_XS  24544    // [128][64]
#define OFF_GS  32736    // [128][64]
#define OFF_H1S 40928    // [32][64]
#define OFF_C1S 42976    // [32][64]
#define OFF_H2S 45024    // [16][64]
#define OFF_C2S 46048    // [16][64]
#define OFF_H3S 47072    // [8][64]
#define OFF_C3S 47584    // [8][64]
#define SMEM_FLOATS 48096
#define SMEM_BYTES  (SMEM_FLOATS * 4)

__device__ __forceinline__ unsigned long long pack2(float a, float b) {
    unsigned long long r;
    asm("mov.b64 %0, {%1, %2};" : "=l"(r) : "f"(a), "f"(b));
    return r;
}
__device__ __forceinline__ unsigned long long fma2(unsigned long long a,
                                                   unsigned long long b,
                                                   unsigned long long c) {
    unsigned long long d;
    asm("fma.rn.f32x2 %0, %1, %2, %3;" : "=l"(d) : "l"(a), "l"(b), "l"(c));
    return d;
}
__device__ __forceinline__ float2 u2f2(unsigned long long v) {
    float2 r;
    asm("mov.b64 {%0, %1}, %2;" : "=f"(r.x), "=f"(r.y) : "l"(v));
    return r;
}
__device__ __forceinline__ float sigf(float v) {
    return __fdividef(1.f, 1.f + __expf(-v));
}
// tanh(x) = 1 - 2/(exp(2x)+1); saturates correctly at +/-inf (no NaN).
__device__ __forceinline__ float tanhf_(float v) {
    return 1.f - __fdividef(2.f, __expf(2.f * v) + 1.f);
}

// Gates for one layer: each thread (gg in 0..3, bl in 0..63) computes
// Gtot/4 gate rows for one batch column, as f32x2 gate-pairs.
template <int Gtot, int Kx, int Kh>
__device__ __forceinline__ void gates_compute(const float* __restrict__ WX,
                                              const float* __restrict__ WH,
                                              const float* __restrict__ Bv,
                                              const float* __restrict__ Xin,
                                              const float* __restrict__ Hin,
                                              float* __restrict__ GS,
                                              int gg, int bl) {
    constexpr int PG = Gtot / 4;   // gate rows per thread
    constexpr int NP = PG / 2;     // f32x2 accumulators
    const int g0 = gg * PG;
    unsigned long long acc[NP];
    const unsigned long long* bp = (const unsigned long long*)(Bv + g0);
#pragma unroll
    for (int p = 0; p < NP; p++) acc[p] = bp[p];

#pragma unroll 4
    for (int k = 0; k < Kx; k++) {
        float xv = Xin[k * BT + bl];
        unsigned long long xx = pack2(xv, xv);
        const ulonglong2* wp = (const ulonglong2*)(WX + k * Gtot + g0);
#pragma unroll
        for (int p = 0; p < NP / 2; p++) {
            ulonglong2 w = wp[p];
            acc[2 * p]     = fma2(xx, w.x, acc[2 * p]);
            acc[2 * p + 1] = fma2(xx, w.y, acc[2 * p + 1]);
        }
    }
#pragma unroll 4
    for (int k = 0; k < Kh; k++) {
        float hv = Hin[k * BT + bl];
        unsigned long long xx = pack2(hv, hv);
        const ulonglong2* wp = (const ulonglong2*)(WH + k * Gtot + g0);
#pragma unroll
        for (int p = 0; p < NP / 2; p++) {
            ulonglong2 w = wp[p];
            acc[2 * p]     = fma2(xx, w.x, acc[2 * p]);
            acc[2 * p + 1] = fma2(xx, w.y, acc[2 * p + 1]);
        }
    }
#pragma unroll
    for (int p = 0; p < NP; p++) {
        float2 v = u2f2(acc[p]);
        GS[(g0 + 2 * p) * BT + bl]     = v.x;
        GS[(g0 + 2 * p + 1) * BT + bl] = v.y;
    }
}

// LSTM cell elementwise update. Gate order i,f,g,o (PyTorch).
template <int H>
__device__ __forceinline__ void ew_compute(const float* __restrict__ GS,
                                           float* __restrict__ HS,
                                           float* __restrict__ CS,
                                           int gg, int bl) {
    constexpr int PJ = H / 4;
    const int j0 = gg * PJ;
#pragma unroll
    for (int jj = 0; jj < PJ; jj++) {
        int j = j0 + jj;
        float iv = sigf(GS[j * BT + bl]);
        float fv = sigf(GS[(H + j) * BT + bl]);
        float gv = tanhf_(GS[(2 * H + j) * BT + bl]);
        float ov = sigf(GS[(3 * H + j) * BT + bl]);
        float c = fv * CS[j * BT + bl] + iv * gv;
        CS[j * BT + bl] = c;
        HS[j * BT + bl] = ov * tanhf_(c);
    }
}

extern __shared__ float smem[];

__global__ __launch_bounds__(NTH, 1) void lstm3_fused_kernel(
    const float* __restrict__ x,
    const float* __restrict__ w_ih1, const float* __restrict__ w_hh1,
    const float* __restrict__ b_ih1, const float* __restrict__ b_hh1,
    const float* __restrict__ w_ih2, const float* __restrict__ w_hh2,
    const float* __restrict__ b_ih2, const float* __restrict__ b_hh2,
    const float* __restrict__ w_ih3, const float* __restrict__ w_hh3,
    const float* __restrict__ b_ih3, const float* __restrict__ b_hh3,
    const float* __restrict__ fc_w, const float* __restrict__ fc_b,
    float* __restrict__ out) {
    const int tid = threadIdx.x;
    const int b0 = blockIdx.x * BT;

    float* W1X = smem + OFF_W1X;
    float* W1H = smem + OFF_W1H;
    float* B1  = smem + OFF_B1;
    float* W2X = smem + OFF_W2X;
    float* W2H = smem + OFF_W2H;
    float* B2  = smem + OFF_B2;
    float* W3X = smem + OFF_W3X;
    float* W3H = smem + OFF_W3H;
    float* B3  = smem + OFF_B3;
    float* XS  = smem + OFF_XS;
    float* GS  = smem + OFF_GS;
    float* H1S = smem + OFF_H1S;
    float* C1S = smem + OFF_C1S;
    float* H2S = smem + OFF_H2S;
    float* C2S = smem + OFF_C2S;
    float* H3S = smem + OFF_H3S;
    float* C3S = smem + OFF_C3S;

    // ---- load weights transposed to [k][g] (one-time) ----
    for (int i = tid; i < G1 * DIN; i += NTH) { int g = i / DIN, k = i % DIN; W1X[k * G1 + g] = w_ih1[i]; }
    for (int i = tid; i < G1 * H1;  i += NTH) { int g = i / H1,  k = i % H1;  W1H[k * G1 + g] = w_hh1[i]; }
    for (int i = tid; i < G1;       i += NTH) { B1[i] = b_ih1[i] + b_hh1[i]; }
    for (int i = tid; i < G2 * H1;  i += NTH) { int g = i / H1,  k = i % H1;  W2X[k * G2 + g] = w_ih2[i]; }
    for (int i = tid; i < G2 * H2;  i += NTH) { int g = i / H2,  k = i % H2;  W2H[k * G2 + g] = w_hh2[i]; }
    for (int i = tid; i < G2;       i += NTH) { B2[i] = b_ih2[i] + b_hh2[i]; }
    for (int i = tid; i < G3 * H2;  i += NTH) { int g = i / H2,  k = i % H2;  W3X[k * G3 + g] = w_ih3[i]; }
    for (int i = tid; i < G3 * H3;  i += NTH) { int g = i / H3,  k = i % H3;  W3H[k * G3 + g] = w_hh3[i]; }
    for (int i = tid; i < G3;       i += NTH) { B3[i] = b_ih3[i] + b_hh3[i]; }
    // zero states
    for (int i = tid; i < H1 * BT; i += NTH) { H1S[i] = 0.f; C1S[i] = 0.f; }
    for (int i = tid; i < H2 * BT; i += NTH) { H2S[i] = 0.f; C2S[i] = 0.f; }
    for (int i = tid; i < H3 * BT; i += NTH) { H3S[i] = 0.f; C3S[i] = 0.f; }

    const int gg = tid >> 6;   // 0..3: gate-group / k-quarter
    const int bl = tid & 63;   // local batch column

    // x prefetch registers: thread loads k in [gg*32, gg*32+32) for batch bl
    float4 xr[8];
    const float* xbase = x + ((size_t)(b0 + bl) * TT) * DIN + gg * 32;

#define LOADX(t)                                                        \
    {                                                                   \
        const float4* p = (const float4*)(xbase + (size_t)(t) * DIN);   \
        _Pragma("unroll") for (int i = 0; i < 8; i++) xr[i] = p[i];     \
    }
#define STOREX()                                                        \
    {                                                                   \
        _Pragma("unroll") for (int i = 0; i < 8; i++) {                 \
            int k = gg * 32 + i * 4;                                    \
            XS[(k + 0) * BT + bl] = xr[i].x;                            \
            XS[(k + 1) * BT + bl] = xr[i].y;                            \
            XS[(k + 2) * BT + bl] = xr[i].z;                            \
            XS[(k + 3) * BT + bl] = xr[i].w;                            \
        }                                                               \
    }

    LOADX(0);
    __syncthreads();   // weights + zeroed state visible
    STOREX();
    __syncthreads();

    for (int t = 0; t < TT; ++t) {
        if (t + 1 < TT) LOADX(t + 1);

        // layer 1 gates: [64b,128g] = XS(128) + H1S(32)
        gates_compute<G1, DIN, H1>(W1X, W1H, B1, XS, H1S, GS, gg, bl);
        __syncthreads();
        ew_compute<H1>(GS, H1S, C1S, gg, bl);
        __syncthreads();

        // layer 2 gates: [64b,64g] = H1S(32) + H2S(16)
        gates_compute<G2, H1, H2>(W2X, W2H, B2, H1S, H2S, GS, gg, bl);
        __syncthreads();
        ew_compute<H2>(GS, H2S, C2S, gg, bl);
        __syncthreads();

        // layer 3 gates: [64b,32g] = H2S(16) + H3S(8)
        gates_compute<G3, H2, H3>(W3X, W3H, B3, H2S, H3S, GS, gg, bl);
        __syncthreads();
        ew_compute<H3>(GS, H3S, C3S, gg, bl);
        __syncthreads();

        if (t + 1 < TT) { STOREX(); }
        __syncthreads();
    }

    // final FC: out[b] = sum_j fc_w[j] * h3[b][j] + fc_b[0]
    if (tid < BT) {
        float acc = fc_b[0];
#pragma unroll
        for (int j = 0; j < H3; j++) acc += fc_w[j] * H3S[j * BT + tid];
        out[b0 + tid] = acc;
    }
}

extern "C" void kernel_launch(void* const* d_in, const int* in_sizes, int n_in,
                              void* d_out, int out_size) {
    (void)in_sizes; (void)n_in; (void)out_size;
    const float* x     = (const float*)d_in[0];
    const float* w_ih1 = (const float*)d_in[1];
    const float* w_hh1 = (const float*)d_in[2];
    const float* b_ih1 = (const float*)d_in[3];
    const float* b_hh1 = (const float*)d_in[4];
    const float* w_ih2 = (const float*)d_in[5];
    const float* w_hh2 = (const float*)d_in[6];
    const float* b_ih2 = (const float*)d_in[7];
    const float* b_hh2 = (const float*)d_in[8];
    const float* w_ih3 = (const float*)d_in[9];
    const float* w_hh3 = (const float*)d_in[10];
    const float* b_ih3 = (const float*)d_in[11];
    const float* b_hh3 = (const float*)d_in[12];
    const float* fc_w  = (const float*)d_in[13];
    const float* fc_b  = (const float*)d_in[14];
    float* out = (float*)d_out;

    cudaFuncSetAttribute(lstm3_fused_kernel,
                         cudaFuncAttributeMaxDynamicSharedMemorySize, SMEM_BYTES);
    lstm3_fused_kernel<<<NCTA, NTH, SMEM_BYTES>>>(
        x, w_ih1, w_hh1, b_ih1, b_hh1, w_ih2, w_hh2, b_ih2, b_hh2,
        w_ih3, w_hh3, b_ih3, b_hh3, fc_w, fc_b, out);
}

// round 2
// speedup vs baseline: 1.0022x; 1.0022x over previous
#include <cuda_runtime.h>

#define TT   64
#define BATCH 8192
#define DIN  128
#define BT   64
#define NTH  256
#define NCTA (BATCH / BT)

#define G1 128
#define G2 64
#define G3 32
#define H1 32
#define H2 16
#define H3 8

// shared-memory float offsets
#define OFF_W1X 0        // [128][128]  (k-major, [k][g])
#define OFF_W1H 16384    // [32][128]
#define OFF_B1  20480    // [128]
#define OFF_W2X 20608    // [32][64]
#define OFF_W2H 22656    // [16][64]
#define OFF_B2  23680    // [64]
#define OFF_W3X 23744    // [16][32]
#define OFF_W3H 24256    // [8][32]
#define OFF_B3  24512    // [32]
#define OFF_XS  24544    // [128][64]
#define OFF_GS  32736    // [128][64]
#define OFF_H1S 40928    // [32][64]
#define OFF_C1S 42976    // [32][64]
#define OFF_H2S 45024    // [16][64]
#define OFF_C2S 46048    // [16][64]
#define OFF_H3S 47072    // [8][64]
#define OFF_C3S 47584    // [8][64]
#define SMEM_FLOATS 48096
#define SMEM_BYTES  (SMEM_FLOATS * 4)

typedef unsigned long long u64;

__device__ __forceinline__ u64 pack2(float a, float b) {
    u64 r;
    asm("mov.b64 %0, {%1, %2};" : "=l"(r) : "f"(a), "f"(b));
    return r;
}
__device__ __forceinline__ u64 fma2(u64 a, u64 b, u64 c) {
    u64 d;
    asm("fma.rn.f32x2 %0, %1, %2, %3;" : "=l"(d) : "l"(a), "l"(b), "l"(c));
    return d;
}
__device__ __forceinline__ float sigf(float v) {
    return __fdividef(1.f, 1.f + __expf(-v));
}
// tanh(x) = 1 - 2/(exp(2x)+1); saturates correctly at +/-inf (no NaN).
__device__ __forceinline__ float tanhf_(float v) {
    return 1.f - __fdividef(2.f, __expf(2.f * v) + 1.f);
}

// Accumulate one weight-source into acc[4][NBP].
// Each thread: 4 gate rows (g0..g0+3) x NBP batch-pairs (f32x2 over batch).
// Per k: 1 LDS.128 (weights) + <=2 LDS.128 (x pairs) + 4 packs + 4*NBP fma2.
template <int Gtot, int Ksrc, int NBP>
__device__ __forceinline__ void gates_accum(const float* __restrict__ W,
                                            const float* __restrict__ Src,
                                            u64 acc[4][NBP],
                                            int g0, int b0l) {
#pragma unroll 2
    for (int k = 0; k < Ksrc; k++) {
        float4 w4 = *(const float4*)(W + k * Gtot + g0);
        u64 wd0 = pack2(w4.x, w4.x);
        u64 wd1 = pack2(w4.y, w4.y);
        u64 wd2 = pack2(w4.z, w4.z);
        u64 wd3 = pack2(w4.w, w4.w);
        u64 xp[NBP];
        if (NBP == 4) {
            ulonglong2 a = *(const ulonglong2*)(Src + k * BT + b0l);
            ulonglong2 b = *(const ulonglong2*)(Src + k * BT + b0l + 4);
            xp[0] = a.x; xp[1] = a.y; xp[2] = b.x; xp[3] = b.y;
        } else if (NBP == 2) {
            ulonglong2 a = *(const ulonglong2*)(Src + k * BT + b0l);
            xp[0] = a.x; xp[1] = a.y;
        } else {
            xp[0] = *(const u64*)(Src + k * BT + b0l);
        }
#pragma unroll
        for (int j = 0; j < NBP; j++) {
            acc[0][j] = fma2(xp[j], wd0, acc[0][j]);
            acc[1][j] = fma2(xp[j], wd1, acc[1][j]);
            acc[2][j] = fma2(xp[j], wd2, acc[2][j]);
            acc[3][j] = fma2(xp[j], wd3, acc[3][j]);
        }
    }
}

template <int Gtot, int Kx, int Kh, int NBP>
__device__ __forceinline__ void gates_compute(const float* __restrict__ WX,
                                              const float* __restrict__ WH,
                                              const float* __restrict__ Bv,
                                              const float* __restrict__ Xin,
                                              const float* __restrict__ Hin,
                                              float* __restrict__ GS,
                                              int tid) {
    constexpr int NBG = 32 / NBP;           // batch-pair groups
    static_assert((Gtot / 4) * NBG == NTH, "thread coverage");
    const int ggrp = tid / NBG;
    const int bgrp = tid % NBG;
    const int g0 = ggrp * 4;
    const int b0l = bgrp * NBP * 2;

    u64 acc[4][NBP];
#pragma unroll
    for (int i = 0; i < 4; i++) {
        float bv = Bv[g0 + i];
        u64 bd = pack2(bv, bv);
#pragma unroll
        for (int j = 0; j < NBP; j++) acc[i][j] = bd;
    }

    gates_accum<Gtot, Kx, NBP>(WX, Xin, acc, g0, b0l);
    gates_accum<Gtot, Kh, NBP>(WH, Hin, acc, g0, b0l);

#pragma unroll
    for (int i = 0; i < 4; i++) {
        u64* gp = (u64*)(GS + (g0 + i) * BT + b0l);
#pragma unroll
        for (int j = 0; j < NBP; j++) gp[j] = acc[i][j];
    }
}

// LSTM cell elementwise update. Gate order i,f,g,o (PyTorch).
template <int H>
__device__ __forceinline__ void ew_compute(const float* __restrict__ GS,
                                           float* __restrict__ HS,
                                           float* __restrict__ CS,
                                           int gg, int bl) {
    constexpr int PJ = H / 4;
    const int j0 = gg * PJ;
#pragma unroll
    for (int jj = 0; jj < PJ; jj++) {
        int j = j0 + jj;
        float iv = sigf(GS[j * BT + bl]);
        float fv = sigf(GS[(H + j) * BT + bl]);
        float gv = tanhf_(GS[(2 * H + j) * BT + bl]);
        float ov = sigf(GS[(3 * H + j) * BT + bl]);
        float c = fv * CS[j * BT + bl] + iv * gv;
        CS[j * BT + bl] = c;
        HS[j * BT + bl] = ov * tanhf_(c);
    }
}

extern __shared__ float smem[];

__global__ __launch_bounds__(NTH, 1) void lstm3_fused_kernel(
    const float* __restrict__ x,
    const float* __restrict__ w_ih1, const float* __restrict__ w_hh1,
    const float* __restrict__ b_ih1, const float* __restrict__ b_hh1,
    const float* __restrict__ w_ih2, const float* __restrict__ w_hh2,
    const float* __restrict__ b_ih2, const float* __restrict__ b_hh2,
    const float* __restrict__ w_ih3, const float* __restrict__ w_hh3,
    const float* __restrict__ b_ih3, const float* __restrict__ b_hh3,
    const float* __restrict__ fc_w, const float* __restrict__ fc_b,
    float* __restrict__ out) {
    const int tid = threadIdx.x;
    const int b0 = blockIdx.x * BT;

    float* W1X = smem + OFF_W1X;
    float* W1H = smem + OFF_W1H;
    float* B1  = smem + OFF_B1;
    float* W2X = smem + OFF_W2X;
    float* W2H = smem + OFF_W2H;
    float* B2  = smem + OFF_B2;
    float* W3X = smem + OFF_W3X;
    float* W3H = smem + OFF_W3H;
    float* B3  = smem + OFF_B3;
    float* XS  = smem + OFF_XS;
    float* GS  = smem + OFF_GS;
    float* H1S = smem + OFF_H1S;
    float* C1S = smem + OFF_C1S;
    float* H2S = smem + OFF_H2S;
    float* C2S = smem + OFF_C2S;
    float* H3S = smem + OFF_H3S;
    float* C3S = smem + OFF_C3S;

    // ---- load weights transposed to [k][g] (one-time) ----
    for (int i = tid; i < G1 * DIN; i += NTH) { int g = i / DIN, k = i % DIN; W1X[k * G1 + g] = w_ih1[i]; }
    for (int i = tid; i < G1 * H1;  i += NTH) { int g = i / H1,  k = i % H1;  W1H[k * G1 + g] = w_hh1[i]; }
    for (int i = tid; i < G1;       i += NTH) { B1[i] = b_ih1[i] + b_hh1[i]; }
    for (int i = tid; i < G2 * H1;  i += NTH) { int g = i / H1,  k = i % H1;  W2X[k * G2 + g] = w_ih2[i]; }
    for (int i = tid; i < G2 * H2;  i += NTH) { int g = i / H2,  k = i % H2;  W2H[k * G2 + g] = w_hh2[i]; }
    for (int i = tid; i < G2;       i += NTH) { B2[i] = b_ih2[i] + b_hh2[i]; }
    for (int i = tid; i < G3 * H2;  i += NTH) { int g = i / H2,  k = i % H2;  W3X[k * G3 + g] = w_ih3[i]; }
    for (int i = tid; i < G3 * H3;  i += NTH) { int g = i / H3,  k = i % H3;  W3H[k * G3 + g] = w_hh3[i]; }
    for (int i = tid; i < G3;       i += NTH) { B3[i] = b_ih3[i] + b_hh3[i]; }
    // zero states
    for (int i = tid; i < H1 * BT; i += NTH) { H1S[i] = 0.f; C1S[i] = 0.f; }
    for (int i = tid; i < H2 * BT; i += NTH) { H2S[i] = 0.f; C2S[i] = 0.f; }
    for (int i = tid; i < H3 * BT; i += NTH) { H3S[i] = 0.f; C3S[i] = 0.f; }

    const int gg = tid >> 6;   // for ew + x staging
    const int bl = tid & 63;

    // x prefetch registers: thread loads k in [gg*32, gg*32+32) for batch bl
    float4 xr[8];
    const float* xbase = x + ((size_t)(b0 + bl) * TT) * DIN + gg * 32;

#define LOADX(t)                                                        \
    {                                                                   \
        const float4* p = (const float4*)(xbase + (size_t)(t) * DIN);   \
        _Pragma("unroll") for (int i = 0; i < 8; i++) xr[i] = p[i];     \
    }
#define STOREX()                                                        \
    {                                                                   \
        _Pragma("unroll") for (int i = 0; i < 8; i++) {                 \
            int k = gg * 32 + i * 4;                                    \
            XS[(k + 0) * BT + bl] = xr[i].x;                            \
            XS[(k + 1) * BT + bl] = xr[i].y;                            \
            XS[(k + 2) * BT + bl] = xr[i].z;                            \
            XS[(k + 3) * BT + bl] = xr[i].w;                            \
        }                                                               \
    }

    LOADX(0);
    __syncthreads();   // weights + zeroed state visible
    STOREX();
    __syncthreads();

    for (int t = 0; t < TT; ++t) {
        if (t + 1 < TT) LOADX(t + 1);

        // layer 1 gates: 128 gates, K = 128(x) + 32(h), NBP=4
        gates_compute<G1, DIN, H1, 4>(W1X, W1H, B1, XS, H1S, GS, tid);
        __syncthreads();
        ew_compute<H1>(GS, H1S, C1S, gg, bl);
        __syncthreads();

        // layer 2 gates: 64 gates, K = 32 + 16, NBP=2
        gates_compute<G2, H1, H2, 2>(W2X, W2H, B2, H1S, H2S, GS, tid);
        __syncthreads();
        ew_compute<H2>(GS, H2S, C2S, gg, bl);
        __syncthreads();

        // layer 3 gates: 32 gates, K = 16 + 8, NBP=1
        gates_compute<G3, H2, H3, 1>(W3X, W3H, B3, H2S, H3S, GS, tid);
        __syncthreads();
        ew_compute<H3>(GS, H3S, C3S, gg, bl);
        __syncthreads();

        if (t + 1 < TT) { STOREX(); }
        __syncthreads();
    }

    // final FC: out[b] = sum_j fc_w[j] * h3[b][j] + fc_b[0]
    if (tid < BT) {
        float acc = fc_b[0];
#pragma unroll
        for (int j = 0; j < H3; j++) acc += fc_w[j] * H3S[j * BT + tid];
        out[b0 + tid] = acc;
    }
}

extern "C" void kernel_launch(void* const* d_in, const int* in_sizes, int n_in,
                              void* d_out, int out_size) {
    (void)in_sizes; (void)n_in; (void)out_size;
    const float* x     = (const float*)d_in[0];
    const float* w_ih1 = (const float*)d_in[1];
    const float* w_hh1 = (const float*)d_in[2];
    const float* b_ih1 = (const float*)d_in[3];
    const float* b_hh1 = (const float*)d_in[4];
    const float* w_ih2 = (const float*)d_in[5];
    const float* w_hh2 = (const float*)d_in[6];
    const float* b_ih2 = (const float*)d_in[7];
    const float* b_hh2 = (const float*)d_in[8];
    const float* w_ih3 = (const float*)d_in[9];
    const float* w_hh3 = (const float*)d_in[10];
    const float* b_ih3 = (const float*)d_in[11];
    const float* b_hh3 = (const float*)d_in[12];
    const float* fc_w  = (const float*)d_in[13];
    const float* fc_b  = (const float*)d_in[14];
    float* out = (float*)d_out;

    cudaFuncSetAttribute(lstm3_fused_kernel,
                         cudaFuncAttributeMaxDynamicSharedMemorySize, SMEM_BYTES);
    lstm3_fused_kernel<<<NCTA, NTH, SMEM_BYTES>>>(
        x, w_ih1, w_hh1, b_ih1, b_hh1, w_ih2, w_hh2, b_ih2, b_hh2,
        w_ih3, w_hh3, b_ih3, b_hh3, fc_w, fc_b, out);
}

// round 3
// speedup vs baseline: 1.3492x; 1.3462x over previous
#include <cuda_runtime.h>

typedef unsigned long long u64;

#define TT    64
#define BATCH 8192
#define DIN   128
#define BT    64
#define NCTA  (BATCH / BT)

#define G1 128
#define G2 64
#define G3 32
#define H1 32
#define H2 16
#define H3 8

// ---------------- phase A (XG = x @ W_ih1^T + b1) ----------------
#define TPB 8            // timesteps per phase-A block
#define NTA 128          // phase-A threads
#define WS_STRIDE 132    // padded [k][g] weight tile
#define XT_STRIDE 68     // padded [k][b] x tile
#define A_SMEM_FLOATS (DIN * WS_STRIDE + DIN * XT_STRIDE)
#define A_SMEM_BYTES  (A_SMEM_FLOATS * 4)

// ---------------- phase B (recurrent) ----------------
#define NTB 512
// smem float offsets
#define OFF_W1H 0        // [32k][128g]
#define OFF_W2X 4096     // [32k][64g]
#define OFF_W2H 6144     // [16k][64g]
#define OFF_B2  7168     // [64]
#define OFF_W3X 7232     // [16k][32g]
#define OFF_W3H 7744     // [8k][32g]
#define OFF_B3  8000     // [32]
#define OFF_GS  8032     // [128][64]
#define OFF_H1S 16224    // [32][64]
#define OFF_C1S 18272
#define OFF_H2S 20320    // [16][64]
#define OFF_C2S 21344
#define OFF_H3S 22368    // [8][64]
#define OFF_C3S 22880
#define B_SMEM_FLOATS 23392
#define B_SMEM_BYTES  (B_SMEM_FLOATS * 4)

// 256 MB scratch: XG[cta][t][g][bl]
__device__ float g_xg[(size_t)NCTA * TT * G1 * BT];

__device__ __forceinline__ u64 pack2(float a, float b) {
    u64 r;
    asm("mov.b64 %0, {%1, %2};" : "=l"(r) : "f"(a), "f"(b));
    return r;
}
__device__ __forceinline__ u64 fma2(u64 a, u64 b, u64 c) {
    u64 d;
    asm("fma.rn.f32x2 %0, %1, %2, %3;" : "=l"(d) : "l"(a), "l"(b), "l"(c));
    return d;
}
__device__ __forceinline__ float sigf(float v) {
    return __fdividef(1.f, 1.f + __expf(-v));
}
__device__ __forceinline__ float tanhf_(float v) {
    return 1.f - __fdividef(2.f, __expf(2.f * v) + 1.f);
}

// Generic MAC loop: acc[GPT gates][NBP batch-pairs] += W[k][g0..] * S[k][b0l..]
template <int WSTR, int SSTR, int GPT, int NBP, int K>
__device__ __forceinline__ void accum(const float* __restrict__ W,
                                      const float* __restrict__ S,
                                      u64 (&acc)[GPT][NBP], int g0, int b0l) {
#pragma unroll 2
    for (int k = 0; k < K; k++) {
        const float* wr = W + k * WSTR + g0;
        float wv[GPT];
        if constexpr (GPT == 8) {
            float4 a = *(const float4*)wr;
            float4 b = *(const float4*)(wr + 4);
            wv[0] = a.x; wv[1] = a.y; wv[2] = a.z; wv[3] = a.w;
            wv[4] = b.x; wv[5] = b.y; wv[6] = b.z; wv[7] = b.w;
        } else if constexpr (GPT == 4) {
            float4 a = *(const float4*)wr;
            wv[0] = a.x; wv[1] = a.y; wv[2] = a.z; wv[3] = a.w;
        } else {
            float2 a = *(const float2*)wr;
            wv[0] = a.x; wv[1] = a.y;
        }
        const float* sr = S + k * SSTR + b0l;
        u64 xp[NBP];
        if constexpr (NBP == 4) {
            ulonglong2 a = *(const ulonglong2*)sr;
            ulonglong2 b = *(const ulonglong2*)(sr + 4);
            xp[0] = a.x; xp[1] = a.y; xp[2] = b.x; xp[3] = b.y;
        } else if constexpr (NBP == 2) {
            ulonglong2 a = *(const ulonglong2*)sr;
            xp[0] = a.x; xp[1] = a.y;
        } else {
            xp[0] = *(const u64*)sr;
        }
        u64 wd[GPT];
#pragma unroll
        for (int i = 0; i < GPT; i++) wd[i] = pack2(wv[i], wv[i]);
#pragma unroll
        for (int i = 0; i < GPT; i++)
#pragma unroll
            for (int j = 0; j < NBP; j++)
                acc[i][j] = fma2(xp[j], wd[i], acc[i][j]);
    }
}

// ======================= PHASE A =======================
extern __shared__ float smemA[];
__global__ __launch_bounds__(NTA) void lstm_phaseA(
    const float* __restrict__ x,
    const float* __restrict__ w_ih1,
    const float* __restrict__ b_ih1,
    const float* __restrict__ b_hh1) {
    float* WS = smemA;                      // [128k][132]
    float* XT = smemA + DIN * WS_STRIDE;    // [128k][68]
    const int tid = threadIdx.x;
    const int wrp = tid >> 5, ln = tid & 31;
    const int cta = blockIdx.y;
    const int tg  = blockIdx.x;
    const int b0  = cta * BT;

    // stage W transposed: w_ih1[g][k] -> WS[k][g]
    for (int idx = tid; idx < G1 * DIN; idx += NTA) {
        int g = idx / DIN, k = idx % DIN;
        WS[k * WS_STRIDE + g] = w_ih1[idx];
    }
    const int gg = tid >> 3, bg = tid & 7;
    const int g0 = gg * 8, b0l = bg * 8;
    u64 bd[8];
#pragma unroll
    for (int i = 0; i < 8; i++) {
        float bv = b_ih1[g0 + i] + b_hh1[g0 + i];
        bd[i] = pack2(bv, bv);
    }
    __syncthreads();

    for (int tt = 0; tt < TPB; tt++) {
        const int t = tg * TPB + tt;
        // stage x tile transposed: warp handles rows [wrp*16, wrp*16+16)
        for (int r = 0; r < 16; r++) {
            int bl = wrp * 16 + r;
            const float* xrow = x + ((size_t)(b0 + bl) * TT + t) * DIN;
#pragma unroll
            for (int i = 0; i < 4; i++)
                XT[(i * 32 + ln) * XT_STRIDE + bl] = xrow[i * 32 + ln];
        }
        __syncthreads();

        u64 acc[8][4];
#pragma unroll
        for (int i = 0; i < 8; i++)
#pragma unroll
            for (int j = 0; j < 4; j++) acc[i][j] = bd[i];

        accum<WS_STRIDE, XT_STRIDE, 8, 4, DIN>(WS, XT, acc, g0, b0l);

        float* xgout = g_xg + ((size_t)(cta * TT + t) * G1) * BT;
#pragma unroll
        for (int i = 0; i < 8; i++) {
            ulonglong2 v0, v1;
            v0.x = acc[i][0]; v0.y = acc[i][1];
            v1.x = acc[i][2]; v1.y = acc[i][3];
            *(ulonglong2*)(xgout + (g0 + i) * BT + b0l)     = v0;
            *(ulonglong2*)(xgout + (g0 + i) * BT + b0l + 4) = v1;
        }
        __syncthreads();   // before restaging XT
    }
}

// ======================= PHASE B =======================
template <int GPT, int NBP>
__device__ __forceinline__ void store_gates(float* __restrict__ GS,
                                            u64 (&acc)[GPT][NBP],
                                            int g0, int b0l) {
#pragma unroll
    for (int i = 0; i < GPT; i++)
#pragma unroll
        for (int j = 0; j < NBP; j++)
            *(u64*)(GS + (g0 + i) * BT + b0l + 2 * j) = acc[i][j];
}

template <int H>
__device__ __forceinline__ void ew(const float* __restrict__ GS,
                                   float* __restrict__ HS,
                                   float* __restrict__ CS,
                                   int jq, int bl) {
    constexpr int PJ = (H * BT) / NTB;   // H/8
#pragma unroll
    for (int jj = 0; jj < PJ; jj++) {
        int j = jq * PJ + jj;
        float iv = sigf(GS[j * BT + bl]);
        float fv = sigf(GS[(H + j) * BT + bl]);
        float gv = tanhf_(GS[(2 * H + j) * BT + bl]);
        float ov = sigf(GS[(3 * H + j) * BT + bl]);
        float c = fv * CS[j * BT + bl] + iv * gv;
        CS[j * BT + bl] = c;
        HS[j * BT + bl] = ov * tanhf_(c);
    }
}

extern __shared__ float smemB[];
__global__ __launch_bounds__(NTB, 1) void lstm_phaseB(
    const float* __restrict__ w_hh1,
    const float* __restrict__ w_ih2, const float* __restrict__ w_hh2,
    const float* __restrict__ b_ih2, const float* __restrict__ b_hh2,
    const float* __restrict__ w_ih3, const float* __restrict__ w_hh3,
    const float* __restrict__ b_ih3, const float* __restrict__ b_hh3,
    const float* __restrict__ fc_w, const float* __restrict__ fc_b,
    float* __restrict__ out) {
    const int tid = threadIdx.x;
    const int cta = blockIdx.x;

    float* W1H = smemB + OFF_W1H;
    float* W2X = smemB + OFF_W2X;
    float* W2H = smemB + OFF_W2H;
    float* B2  = smemB + OFF_B2;
    float* W3X = smemB + OFF_W3X;
    float* W3H = smemB + OFF_W3H;
    float* B3  = smemB + OFF_B3;
    float* GS  = smemB + OFF_GS;
    float* H1S = smemB + OFF_H1S;
    float* C1S = smemB + OFF_C1S;
    float* H2S = smemB + OFF_H2S;
    float* C2S = smemB + OFF_C2S;
    float* H3S = smemB + OFF_H3S;
    float* C3S = smemB + OFF_C3S;

    // stage weights transposed [k][g]
    for (int i = tid; i < G1 * H1; i += NTB) { int g = i / H1, k = i % H1; W1H[k * G1 + g] = w_hh1[i]; }
    for (int i = tid; i < G2 * H1; i += NTB) { int g = i / H1, k = i % H1; W2X[k * G2 + g] = w_ih2[i]; }
    for (int i = tid; i < G2 * H2; i += NTB) { int g = i / H2, k = i % H2; W2H[k * G2 + g] = w_hh2[i]; }
    for (int i = tid; i < G2;      i += NTB) { B2[i] = b_ih2[i] + b_hh2[i]; }
    for (int i = tid; i < G3 * H2; i += NTB) { int g = i / H2, k = i % H2; W3X[k * G3 + g] = w_ih3[i]; }
    for (int i = tid; i < G3 * H3; i += NTB) { int g = i / H3, k = i % H3; W3H[k * G3 + g] = w_hh3[i]; }
    for (int i = tid; i < G3;      i += NTB) { B3[i] = b_ih3[i] + b_hh3[i]; }
    for (int i = tid; i < H1 * BT; i += NTB) { H1S[i] = 0.f; C1S[i] = 0.f; }
    for (int i = tid; i < H2 * BT; i += NTB) { H2S[i] = 0.f; C2S[i] = 0.f; }
    for (int i = tid; i < H3 * BT; i += NTB) { H3S[i] = 0.f; C3S[i] = 0.f; }

    // layer-1 gate mapping: 4 gates x 4 batch per thread
    const int gg1 = tid >> 4;           // 0..31
    const int bg1 = tid & 15;           // 0..15
    const int g0l1 = gg1 * 4, b0l1 = bg1 * 4;
    // layer-2 mapping: 4 gates x 2 batch
    const int g0l2 = (tid >> 5) * 4;    // 0..60
    const int b0l2 = (tid & 31) * 2;
    // layer-3 mapping: 2 gates x 2 batch
    const int g0l3 = (tid >> 5) * 2;    // 0..30
    const int b0l3 = (tid & 31) * 2;
    // ew mapping
    const int jq = tid >> 6;            // 0..7
    const int bl = tid & 63;

    const float* xgbase = g_xg + (size_t)cta * TT * G1 * BT;

    // prefetch XG(t=0) into registers
    ulonglong2 xga[4];
#pragma unroll
    for (int i = 0; i < 4; i++)
        xga[i] = *(const ulonglong2*)(xgbase + (size_t)(0 * G1 + g0l1 + i) * BT + b0l1);

    __syncthreads();

    for (int t = 0; t < TT; ++t) {
        // ---- layer 1 gates: acc init from XG, += h1 @ W1H ----
        {
            u64 acc[4][2];
#pragma unroll
            for (int i = 0; i < 4; i++) { acc[i][0] = xga[i].x; acc[i][1] = xga[i].y; }
            accum<G1, BT, 4, 2, H1>(W1H, H1S, acc, g0l1, b0l1);
            store_gates<4, 2>(GS, acc, g0l1, b0l1);
        }
        // prefetch next timestep's XG (full timestep of latency cover)
        if (t + 1 < TT) {
#pragma unroll
            for (int i = 0; i < 4; i++)
                xga[i] = *(const ulonglong2*)(xgbase + (size_t)((t + 1) * G1 + g0l1 + i) * BT + b0l1);
        }
        __syncthreads();
        ew<H1>(GS, H1S, C1S, jq, bl);
        __syncthreads();

        // ---- layer 2 ----
        {
            u64 acc[4][1];
#pragma unroll
            for (int i = 0; i < 4; i++) {
                float bv = B2[g0l2 + i];
                acc[i][0] = pack2(bv, bv);
            }
            accum<G2, BT, 4, 1, H1>(W2X, H1S, acc, g0l2, b0l2);
            accum<G2, BT, 4, 1, H2>(W2H, H2S, acc, g0l2, b0l2);
            store_gates<4, 1>(GS, acc, g0l2, b0l2);
        }
        __syncthreads();
        ew<H2>(GS, H2S, C2S, jq, bl);
        __syncthreads();

        // ---- layer 3 ----
        {
            u64 acc[2][1];
#pragma unroll
            for (int i = 0; i < 2; i++) {
                float bv = B3[g0l3 + i];
                acc[i][0] = pack2(bv, bv);
            }
            accum<G3, BT, 2, 1, H2>(W3X, H2S, acc, g0l3, b0l3);
            accum<G3, BT, 2, 1, H3>(W3H, H3S, acc, g0l3, b0l3);
            store_gates<2, 1>(GS, acc, g0l3, b0l3);
        }
        __syncthreads();
        ew<H3>(GS, H3S, C3S, jq, bl);
        __syncthreads();
    }

    // final FC
    if (tid < BT) {
        float acc = fc_b[0];
#pragma unroll
        for (int j = 0; j < H3; j++) acc += fc_w[j] * H3S[j * BT + tid];
        out[cta * BT + tid] = acc;
    }
}

extern "C" void kernel_launch(void* const* d_in, const int* in_sizes, int n_in,
                              void* d_out, int out_size) {
    (void)in_sizes; (void)n_in; (void)out_size;
    const float* x     = (const float*)d_in[0];
    const float* w_ih1 = (const float*)d_in[1];
    const float* w_hh1 = (const float*)d_in[2];
    const float* b_ih1 = (const float*)d_in[3];
    const float* b_hh1 = (const float*)d_in[4];
    const float* w_ih2 = (const float*)d_in[5];
    const float* w_hh2 = (const float*)d_in[6];
    const float* b_ih2 = (const float*)d_in[7];
    const float* b_hh2 = (const float*)d_in[8];
    const float* w_ih3 = (const float*)d_in[9];
    const float* w_hh3 = (const float*)d_in[10];
    const float* b_ih3 = (const float*)d_in[11];
    const float* b_hh3 = (const float*)d_in[12];
    const float* fc_w  = (const float*)d_in[13];
    const float* fc_b  = (const float*)d_in[14];
    float* out = (float*)d_out;

    cudaFuncSetAttribute(lstm_phaseA,
                         cudaFuncAttributeMaxDynamicSharedMemorySize, A_SMEM_BYTES);
    cudaFuncSetAttribute(lstm_phaseB,
                         cudaFuncAttributeMaxDynamicSharedMemorySize, B_SMEM_BYTES);

    dim3 gridA(TT / TPB, NCTA);
    lstm_phaseA<<<gridA, NTA, A_SMEM_BYTES>>>(x, w_ih1, b_ih1, b_hh1);
    lstm_phaseB<<<NCTA, NTB, B_SMEM_BYTES>>>(
        w_hh1, w_ih2, w_hh2, b_ih2, b_hh2,
        w_ih3, w_hh3, b_ih3, b_hh3, fc_w, fc_b, out);
}